// round 3
// baseline (speedup 1.0000x reference)
#include <cuda_runtime.h>
#include <math.h>

#define BATCH 64
#define CDIM  512
#define MDIM  1024
#define KW    5

// ---------------- scratch (static device globals: allocation-guard safe) ----
__device__ float g_pe[CDIM * MDIM];                         // positional embedding (C, M)
__device__ float g_mu_pe[CDIM];                             // mean over M of pe row
__device__ float g_hs[(size_t)BATCH * CDIM * MDIM];         // gated signal hs (B,C,M)
__device__ float g_gate[BATCH * CDIM];
__device__ float g_mu_hb[BATCH * CDIM];
__device__ float g_mu_hs[BATCH * CDIM];

// ---------------- phase 1: positional embedding + its row means ------------
__global__ void pe_kernel() {
    const int c = blockIdx.x;
    const int t = threadIdx.x;
    // div = exp((2i) * (-ln(10000)/C)),  2i = c & ~1
    const float dv = expf((float)(c & ~1) * (-9.210340371976184f / (float)CDIM));
    float* row = g_pe + (size_t)c * MDIM;
    float s = 0.f;
    for (int m = t; m < MDIM; m += 256) {
        float ang = (float)m * dv;
        float v = (c & 1) ? cosf(ang) : sinf(ang);
        row[m] = v;
        s += v;
    }
    __shared__ float red[256];
    red[t] = s;
    __syncthreads();
    for (int o = 128; o > 0; o >>= 1) {
        if (t < o) red[t] += red[t + o];
        __syncthreads();
    }
    if (t == 0) g_mu_pe[c] = red[0] * (1.0f / (float)MDIM);
}

// ---------------- phase 2: per-row means of h_in ---------------------------
__global__ void mean_kernel(const float* __restrict__ hin) {
    const int row = blockIdx.x;                 // b*C + c
    const int t = threadIdx.x;                  // 256 threads, 1024 floats/row
    const float4 v = ((const float4*)(hin + (size_t)row * MDIM))[t];
    float s = v.x + v.y + v.z + v.w;
    __shared__ float red[256];
    red[t] = s;
    __syncthreads();
    for (int o = 128; o > 0; o >>= 1) {
        if (t < o) red[t] += red[t + o];
        __syncthreads();
    }
    if (t == 0) g_mu_hb[row] = red[0] * (1.0f / (float)MDIM);
}

// ---------------- phase 3: depthwise conv over C -> gate, mu_hs ------------
__global__ void gate_kernel(const float* __restrict__ w, const float* __restrict__ bias) {
    const int b = blockIdx.x;
    const int c = threadIdx.x;                  // 512 threads
    __shared__ float ys[CDIM + 4];
    const float y = g_mu_hb[b * CDIM + c] + g_mu_pe[c];
    ys[c + 2] = y;
    if (c < 2) { ys[c] = 0.f; ys[CDIM + 2 + c] = 0.f; }
    __syncthreads();
    float acc = bias[c];
#pragma unroll
    for (int k = 0; k < KW; k++) acc += ys[c + k] * w[c * KW + k];
    const float g = 1.0f / (1.0f + expf(-acc));
    g_gate[b * CDIM + c] = g;
    g_mu_hs[b * CDIM + c] = g * y;
}

// ---------------- phase 4: materialize hs = gate * (hb + pe) ---------------
__global__ void hs_kernel(const float* __restrict__ hin) {
    const int row = blockIdx.x;                 // b*C + c
    const int c = row & (CDIM - 1);
    const int t = threadIdx.x;                  // 256 threads x float4 = 1024
    const float g = g_gate[row];
    const float4 a = ((const float4*)(hin + (size_t)row * MDIM))[t];
    const float4 e = ((const float4*)(g_pe + (size_t)c * MDIM))[t];
    float4 o;
    o.x = g * (a.x + e.x);
    o.y = g * (a.y + e.y);
    o.z = g * (a.z + e.z);
    o.w = g * (a.w + e.w);
    ((float4*)(g_hs + (size_t)row * MDIM))[t] = o;
}

// ---------------- phase 5: dual SYRK + rank-1 corrections ------------------
// cov[b] = (HS HS^T + HB HB^T)/M - mu_hs mu_hs^T - mu_hb mu_hb^T + 1e-8 I
// 128x128 tiles over C=512 (4x4 tile grid), upper-triangular pairs only.
__constant__ int c_ti[10] = {0,0,0,0,1,1,1,2,2,3};
__constant__ int c_tj[10] = {0,1,2,3,1,2,3,2,3,3};

__global__ __launch_bounds__(256, 2)
void syrk_kernel(const float* __restrict__ hin, float* __restrict__ out) {
    const int pair = blockIdx.x;
    const int b    = blockIdx.y;
    const int ti = c_ti[pair];
    const int tj = c_tj[pair];

    __shared__ __align__(16) float sHsI[8][128];
    __shared__ __align__(16) float sHsJ[8][128];
    __shared__ __align__(16) float sHbI[8][128];
    __shared__ __align__(16) float sHbJ[8][128];

    const int tid = threadIdx.x;
    const int tx = tid & 15;          // 0..15 -> d (col) octet
    const int ty = tid >> 4;          // 0..15 -> c (row) octet

    const float* hsI = g_hs + (size_t)(b * CDIM + ti * 128) * MDIM;
    const float* hsJ = g_hs + (size_t)(b * CDIM + tj * 128) * MDIM;
    const float* hbI = hin  + (size_t)(b * CDIM + ti * 128) * MDIM;
    const float* hbJ = hin  + (size_t)(b * CDIM + tj * 128) * MDIM;

    const int lc = tid >> 1;          // 0..127 row within panel
    const int lq = (tid & 1) * 4;     // k offset 0 or 4

    float acc[8][8];
#pragma unroll
    for (int r = 0; r < 8; r++)
#pragma unroll
        for (int s = 0; s < 8; s++) acc[r][s] = 0.f;

    for (int m0 = 0; m0 < MDIM; m0 += 8) {
        const size_t off = (size_t)lc * MDIM + m0 + lq;
        const float4 vA = *(const float4*)(hsI + off);
        const float4 vB = *(const float4*)(hsJ + off);
        const float4 vC = *(const float4*)(hbI + off);
        const float4 vD = *(const float4*)(hbJ + off);

        __syncthreads();   // previous iteration's compute done
        sHsI[lq + 0][lc] = vA.x; sHsI[lq + 1][lc] = vA.y;
        sHsI[lq + 2][lc] = vA.z; sHsI[lq + 3][lc] = vA.w;
        sHsJ[lq + 0][lc] = vB.x; sHsJ[lq + 1][lc] = vB.y;
        sHsJ[lq + 2][lc] = vB.z; sHsJ[lq + 3][lc] = vB.w;
        sHbI[lq + 0][lc] = vC.x; sHbI[lq + 1][lc] = vC.y;
        sHbI[lq + 2][lc] = vC.z; sHbI[lq + 3][lc] = vC.w;
        sHbJ[lq + 0][lc] = vD.x; sHbJ[lq + 1][lc] = vD.y;
        sHbJ[lq + 2][lc] = vD.z; sHbJ[lq + 3][lc] = vD.w;
        __syncthreads();

#pragma unroll
        for (int k = 0; k < 8; k++) {
            float aHS[8], bHS[8], aHB[8], bHB[8];
            float4 x;
            x = *(const float4*)&sHsI[k][ty * 8];     aHS[0]=x.x; aHS[1]=x.y; aHS[2]=x.z; aHS[3]=x.w;
            x = *(const float4*)&sHsI[k][ty * 8 + 4]; aHS[4]=x.x; aHS[5]=x.y; aHS[6]=x.z; aHS[7]=x.w;
            x = *(const float4*)&sHsJ[k][tx * 8];     bHS[0]=x.x; bHS[1]=x.y; bHS[2]=x.z; bHS[3]=x.w;
            x = *(const float4*)&sHsJ[k][tx * 8 + 4]; bHS[4]=x.x; bHS[5]=x.y; bHS[6]=x.z; bHS[7]=x.w;
            x = *(const float4*)&sHbI[k][ty * 8];     aHB[0]=x.x; aHB[1]=x.y; aHB[2]=x.z; aHB[3]=x.w;
            x = *(const float4*)&sHbI[k][ty * 8 + 4]; aHB[4]=x.x; aHB[5]=x.y; aHB[6]=x.z; aHB[7]=x.w;
            x = *(const float4*)&sHbJ[k][tx * 8];     bHB[0]=x.x; bHB[1]=x.y; bHB[2]=x.z; bHB[3]=x.w;
            x = *(const float4*)&sHbJ[k][tx * 8 + 4]; bHB[4]=x.x; bHB[5]=x.y; bHB[6]=x.z; bHB[7]=x.w;
#pragma unroll
            for (int r = 0; r < 8; r++)
#pragma unroll
                for (int s = 0; s < 8; s++)
                    acc[r][s] += aHS[r] * bHS[s] + aHB[r] * bHB[s];
        }
    }

    // epilogue
    const float invM = 1.0f / (float)MDIM;
    const float* muHs = g_mu_hs + b * CDIM;
    const float* muHb = g_mu_hb + b * CDIM;
    const int cbase = ti * 128 + ty * 8;
    const int dbase = tj * 128 + tx * 8;
    float mhsR[8], mhbR[8], mhsC[8], mhbC[8];
#pragma unroll
    for (int r = 0; r < 8; r++) { mhsR[r] = muHs[cbase + r]; mhbR[r] = muHb[cbase + r]; }
#pragma unroll
    for (int s = 0; s < 8; s++) { mhsC[s] = muHs[dbase + s]; mhbC[s] = muHb[dbase + s]; }

    float* ob = out + (size_t)b * CDIM * CDIM;
#pragma unroll
    for (int r = 0; r < 8; r++) {
        const int cc = cbase + r;
#pragma unroll
        for (int s = 0; s < 8; s++) {
            const int dd = dbase + s;
            float v = acc[r][s] * invM - mhsR[r] * mhsC[s] - mhbR[r] * mhbC[s];
            if (cc == dd) v += 1e-8f;
            ob[(size_t)cc * CDIM + dd] = v;
            ob[(size_t)dd * CDIM + cc] = v;
        }
    }
}

// ---------------- launch ----------------------------------------------------
extern "C" void kernel_launch(void* const* d_in, const int* in_sizes, int n_in,
                              void* d_out, int out_size) {
    const float* h_in   = (const float*)d_in[0];   // (B, C, 1, M)
    const float* conv_w = (const float*)d_in[1];   // (C, K)
    const float* conv_b = (const float*)d_in[2];   // (C,)
    float* out = (float*)d_out;                    // (B, C, C)

    pe_kernel<<<CDIM, 256>>>();
    mean_kernel<<<BATCH * CDIM, 256>>>(h_in);
    gate_kernel<<<BATCH, CDIM>>>(conv_w, conv_b);
    hs_kernel<<<BATCH * CDIM, 256>>>(h_in);
    syrk_kernel<<<dim3(10, BATCH), 256>>>(h_in, out);
}

// round 5
// speedup vs baseline: 5.0326x; 5.0326x over previous
#include <cuda_runtime.h>
#include <cuda_bf16.h>
#include <cstdint>
#include <math.h>

#define BATCH 64
#define CDIM  512
#define MDIM  1024
#define KTOT  2048          // concat K: [hs | hb]
#define KW    5
#define TILE  128
#define KC    64            // bf16 per K-chunk (128B row)
#define NCHUNK (KTOT / KC)  // 32
#define T16   16384         // bytes per 128x64 bf16 tile
#define STAGE_BYTES (4 * T16)
#define SMEM_STAGE0 1024
#define SMEM_DYN (SMEM_STAGE0 + 3 * STAGE_BYTES)   // 197632
#define IDESC 0x8200490u    // f32 accum, bf16 a/b, N=128, M=128

// ---- arch-feature gate: tcgen05 only exists in the sm_103a device pass ----
#if defined(__CUDA_ARCH__) && defined(__CUDA_ARCH_HAS_FEATURE__)
#  if __CUDA_ARCH_HAS_FEATURE__(SM103_ALL) || __CUDA_ARCH_HAS_FEATURE__(SM100_ALL)
#    define TC_OK 1
#  endif
#endif
#ifndef TC_OK
#  define TC_OK 0
#endif

// ---------------- scratch (static device globals) ---------------------------
__device__ float g_pe[CDIM * MDIM];
__device__ float g_mu_pe[CDIM];
__device__ float g_gate[BATCH * CDIM];
__device__ float g_mu_hb[BATCH * CDIM];
__device__ float g_mu_hs[BATCH * CDIM];
__device__ __nv_bfloat16 g_hi[(size_t)BATCH * CDIM * KTOT];  // [hs | hb] hi
__device__ __nv_bfloat16 g_lo[(size_t)BATCH * CDIM * KTOT];  // [hs | hb] lo

// ---------------- PTX helpers (arch-portable ones unguarded) ----------------
__device__ __forceinline__ uint32_t smem_u32(const void* p) {
    uint32_t a;
    asm("{ .reg .u64 t; cvta.to.shared.u64 t, %1; cvt.u32.u64 %0, t; }" : "=r"(a) : "l"(p));
    return a;
}

#if TC_OK
__device__ __forceinline__ uint32_t elect_one() {
    uint32_t p;
    asm volatile("{\n\t.reg .pred p;\n\telect.sync _|p, 0xFFFFFFFF;\n\tselp.b32 %0, 1, 0, p;\n\t}" : "=r"(p));
    return p;
}
static constexpr uint64_t DESC_BASE_SW128 =
    (uint64_t(2) << 61) | (uint64_t(1) << 46) | (uint64_t(64) << 32) | (uint64_t(1) << 16);
__device__ __forceinline__ uint64_t make_desc(uint32_t addr) {
    return DESC_BASE_SW128 | ((uint64_t)(addr >> 4) & 0x3FFF);
}
__device__ __forceinline__ void cp16(uint32_t dst, const void* src) {
    asm volatile("cp.async.cg.shared.global [%0], [%1], 16;" :: "r"(dst), "l"(src));
}
__device__ __forceinline__ void mma_ss(uint32_t d, uint64_t a, uint64_t b, uint32_t en) {
    asm volatile(
        "{\n\t.reg .pred p;\n\tsetp.ne.u32 p, %4, 0;\n\t"
        "tcgen05.mma.cta_group::1.kind::f16 [%0], %1, %2, %3, {%5, %5, %5, %5}, p;\n\t}"
        :: "r"(d), "l"(a), "l"(b), "r"(IDESC), "r"(en), "r"(0u) : "memory");
}
#define MBAR_INIT(a, n) asm volatile("mbarrier.init.shared.b64 [%0], %1;" :: "r"(a), "r"(n) : "memory")
#define MBAR_INVAL(a)   asm volatile("mbarrier.inval.shared.b64 [%0];" :: "r"(a) : "memory")
#define TC_COMMIT(a)    asm volatile("tcgen05.commit.cta_group::1.mbarrier::arrive::one.shared::cluster.b64 [%0];" :: "r"(a) : "memory")
__device__ __forceinline__ void mbar_wait(uint32_t mbar, uint32_t parity) {
    asm volatile(
        "{\n\t.reg .pred P1;\n\t"
        "WAIT_LOOP_%=:\n\t"
        "mbarrier.try_wait.parity.acquire.cta.shared::cta.b64 P1, [%0], %1, 0x989680;\n\t"
        "@P1 bra.uni WAIT_DONE_%=;\n\t"
        "bra.uni WAIT_LOOP_%=;\n\t"
        "WAIT_DONE_%=:\n\t}"
        :: "r"(mbar), "r"(parity) : "memory");
}
#define TC_ALLOC(sa, n)   asm volatile("tcgen05.alloc.cta_group::1.sync.aligned.shared::cta.b32 [%0], %1;" :: "r"(sa), "r"(n) : "memory")
#define TC_DEALLOC(t, n)  asm volatile("tcgen05.dealloc.cta_group::1.sync.aligned.b32 %0, %1;" :: "r"(t), "r"(n))
#define TC_RELINQ()       asm volatile("tcgen05.relinquish_alloc_permit.cta_group::1.sync.aligned;")
#define TC_FENCE_AFTER()  asm volatile("tcgen05.fence::after_thread_sync;" ::: "memory")
#define TC_FENCE_BEFORE() asm volatile("tcgen05.fence::before_thread_sync;" ::: "memory")
#define TC_WAIT_LD()      asm volatile("tcgen05.wait::ld.sync.aligned;" ::: "memory")
#define FENCE_PROXY()     asm volatile("fence.proxy.async.shared::cta;" ::: "memory")
#define LDTM_X32(r, a) \
    asm volatile("tcgen05.ld.sync.aligned.32x32b.x32.b32 " \
        "{%0,%1,%2,%3,%4,%5,%6,%7,%8,%9,%10,%11,%12,%13,%14,%15," \
        "%16,%17,%18,%19,%20,%21,%22,%23,%24,%25,%26,%27,%28,%29,%30,%31}, [%32];" \
        : "=r"((r)[0]),"=r"((r)[1]),"=r"((r)[2]),"=r"((r)[3]),"=r"((r)[4]),"=r"((r)[5]),"=r"((r)[6]),"=r"((r)[7]), \
          "=r"((r)[8]),"=r"((r)[9]),"=r"((r)[10]),"=r"((r)[11]),"=r"((r)[12]),"=r"((r)[13]),"=r"((r)[14]),"=r"((r)[15]), \
          "=r"((r)[16]),"=r"((r)[17]),"=r"((r)[18]),"=r"((r)[19]),"=r"((r)[20]),"=r"((r)[21]),"=r"((r)[22]),"=r"((r)[23]), \
          "=r"((r)[24]),"=r"((r)[25]),"=r"((r)[26]),"=r"((r)[27]),"=r"((r)[28]),"=r"((r)[29]),"=r"((r)[30]),"=r"((r)[31]) \
        : "r"(a))
#endif  // TC_OK

// ---------------- phase 1: positional embedding + row means -----------------
__global__ void pe_kernel() {
    const int c = blockIdx.x;
    const int t = threadIdx.x;
    const float dv = expf((float)(c & ~1) * (-9.210340371976184f / (float)CDIM));
    float* row = g_pe + (size_t)c * MDIM;
    float s = 0.f;
    for (int m = t; m < MDIM; m += 256) {
        float ang = (float)m * dv;
        float v = (c & 1) ? cosf(ang) : sinf(ang);
        row[m] = v;
        s += v;
    }
    __shared__ float red[256];
    red[t] = s;
    __syncthreads();
    for (int o = 128; o > 0; o >>= 1) { if (t < o) red[t] += red[t + o]; __syncthreads(); }
    if (t == 0) g_mu_pe[c] = red[0] * (1.0f / (float)MDIM);
}

// ---------------- phase 2: per-row means of h_in ---------------------------
__global__ void mean_kernel(const float* __restrict__ hin) {
    const int row = blockIdx.x;
    const int t = threadIdx.x;
    const float4 v = ((const float4*)(hin + (size_t)row * MDIM))[t];
    float s = v.x + v.y + v.z + v.w;
    __shared__ float red[256];
    red[t] = s;
    __syncthreads();
    for (int o = 128; o > 0; o >>= 1) { if (t < o) red[t] += red[t + o]; __syncthreads(); }
    if (t == 0) g_mu_hb[row] = red[0] * (1.0f / (float)MDIM);
}

// ---------------- phase 3: gate + mu_hs ------------------------------------
__global__ void gate_kernel(const float* __restrict__ w, const float* __restrict__ bias) {
    const int b = blockIdx.x;
    const int c = threadIdx.x;
    __shared__ float ys[CDIM + 4];
    const float y = g_mu_hb[b * CDIM + c] + g_mu_pe[c];
    ys[c + 2] = y;
    if (c < 2) { ys[c] = 0.f; ys[CDIM + 2 + c] = 0.f; }
    __syncthreads();
    float acc = bias[c];
#pragma unroll
    for (int k = 0; k < KW; k++) acc += ys[c + k] * w[c * KW + k];
    const float g = 1.0f / (1.0f + expf(-acc));
    g_gate[b * CDIM + c] = g;
    g_mu_hs[b * CDIM + c] = g * y;
}

// ---------------- phase 4: split into bf16 hi/lo (hs | hb concat on K) -----
__device__ __forceinline__ uint32_t pack_bf2(__nv_bfloat16 x, __nv_bfloat16 y) {
    __nv_bfloat162 v = __halves2bfloat162(x, y);
    return *reinterpret_cast<uint32_t*>(&v);
}
__global__ void split_kernel(const float* __restrict__ hin) {
    const int row = blockIdx.x;                 // b*C + c
    const int c = row & (CDIM - 1);
    const int t = threadIdx.x;                  // 256 threads x 4 elems
    const float g = g_gate[row];
    const float4 a = ((const float4*)(hin + (size_t)row * MDIM))[t];
    const float4 e = ((const float4*)(g_pe + (size_t)c * MDIM))[t];
    float hs[4] = { g * (a.x + e.x), g * (a.y + e.y), g * (a.z + e.z), g * (a.w + e.w) };
    float hb[4] = { a.x, a.y, a.z, a.w };
    __nv_bfloat16 shi[4], slo[4], bhi[4], blo[4];
#pragma unroll
    for (int j = 0; j < 4; j++) {
        shi[j] = __float2bfloat16_rn(hs[j]);
        slo[j] = __float2bfloat16_rn(hs[j] - __bfloat162float(shi[j]));
        bhi[j] = __float2bfloat16_rn(hb[j]);
        blo[j] = __float2bfloat16_rn(hb[j] - __bfloat162float(bhi[j]));
    }
    __nv_bfloat16* dhi = g_hi + (size_t)row * KTOT;
    __nv_bfloat16* dlo = g_lo + (size_t)row * KTOT;
    uint2 w;
    w.x = pack_bf2(shi[0], shi[1]); w.y = pack_bf2(shi[2], shi[3]);
    *(uint2*)(dhi + t * 4) = w;
    w.x = pack_bf2(slo[0], slo[1]); w.y = pack_bf2(slo[2], slo[3]);
    *(uint2*)(dlo + t * 4) = w;
    w.x = pack_bf2(bhi[0], bhi[1]); w.y = pack_bf2(bhi[2], bhi[3]);
    *(uint2*)(dhi + MDIM + t * 4) = w;
    w.x = pack_bf2(blo[0], blo[1]); w.y = pack_bf2(blo[2], blo[3]);
    *(uint2*)(dlo + MDIM + t * 4) = w;
}

// ---------------- phase 5: SYRK --------------------------------------------
__constant__ int c_ti[10] = {0,0,0,0,1,1,1,2,2,3};
__constant__ int c_tj[10] = {0,1,2,3,1,2,3,2,3,3};

__global__ __launch_bounds__(256, 1)
void syrk_tc(float* __restrict__ out) {
    extern __shared__ __align__(1024) char smem[];
    const int tid = threadIdx.x;
    const int pair = blockIdx.x;
    const int b = blockIdx.y;
    const int ti = c_ti[pair], tj = c_tj[pair];

#if TC_OK
    // ======================= tcgen05 bf16 compensated path ==================
    const uint32_t sb = smem_u32(smem);
    const int wid = tid >> 5;
    const int lid = tid & 31;
    const bool diag = (ti == tj);

    if (wid == 0) TC_ALLOC(sb, 128);
    if (tid == 0) { MBAR_INIT(sb + 8, 1); MBAR_INIT(sb + 16, 1); MBAR_INIT(sb + 24, 1); }
    __syncthreads();
    if (wid == 0) TC_RELINQ();
    uint32_t tmem;
    asm volatile("ld.shared.b32 %0, [%1];" : "=r"(tmem) : "r"(sb));

    // 256 threads: thread -> (row = tid>>1, half = tid&1), 64B per thread/tile
    const int row  = tid >> 1;
    const int half = tid & 1;
    const char* Ahi = (const char*)(g_hi + (size_t)(b * CDIM + ti * TILE + row) * KTOT) + half * 64;
    const char* Alo = (const char*)(g_lo + (size_t)(b * CDIM + ti * TILE + row) * KTOT) + half * 64;
    const char* Bhi = (const char*)(g_hi + (size_t)(b * CDIM + tj * TILE + row) * KTOT) + half * 64;
    const char* Blo = (const char*)(g_lo + (size_t)(b * CDIM + tj * TILE + row) * KTOT) + half * 64;
    const uint32_t swbase = (uint32_t)(row * 128 + half * 64);

    auto load_tile = [&](uint32_t dstbase, const char* src) {
#pragma unroll
        for (int q = 0; q < 4; q++) {
            uint32_t off = swbase + q * 16;
            cp16(dstbase + (off ^ ((off >> 3) & 0x70)), src + q * 16);
        }
    };
    auto load_stage = [&](int buf, int chunk) {
        uint32_t stg = sb + SMEM_STAGE0 + buf * STAGE_BYTES;
        const int mB = chunk * 128;             // bytes into the K dimension
        load_tile(stg, Ahi + mB);
        load_tile(stg + T16, Alo + mB);
        if (!diag) {
            load_tile(stg + 2 * T16, Bhi + mB);
            load_tile(stg + 3 * T16, Blo + mB);
        }
    };

    load_stage(0, 0); asm volatile("cp.async.commit_group;" ::: "memory");
    load_stage(1, 1); asm volatile("cp.async.commit_group;" ::: "memory");

    for (int i = 0; i < NCHUNK; i++) {
        const int buf = i % 3;
        if (i >= NCHUNK - 2) { asm volatile("cp.async.wait_group 0;" ::: "memory"); }
        else                 { asm volatile("cp.async.wait_group 1;" ::: "memory"); }
        FENCE_PROXY();
        __syncthreads();

        if (wid == 0 && elect_one()) {
            uint32_t stg = sb + SMEM_STAGE0 + buf * STAGE_BYTES;
            uint64_t dAh = make_desc(stg);
            uint64_t dAl = make_desc(stg + T16);
            uint64_t dBh = diag ? dAh : make_desc(stg + 2 * T16);
            uint64_t dBl = diag ? dAl : make_desc(stg + 3 * T16);
            uint32_t en = (i == 0) ? 0u : 1u;
#pragma unroll
            for (int ks = 0; ks < 4; ks++) { mma_ss(tmem, dAh + ks * 2, dBh + ks * 2, en); en = 1u; }
#pragma unroll
            for (int ks = 0; ks < 4; ks++) mma_ss(tmem, dAh + ks * 2, dBl + ks * 2, 1u);
#pragma unroll
            for (int ks = 0; ks < 4; ks++) mma_ss(tmem, dAl + ks * 2, dBh + ks * 2, 1u);
            TC_COMMIT(sb + 8 + buf * 8);
        }

        if (i >= 1) {
            const int p = i - 1;
            mbar_wait(sb + 8 + (p % 3) * 8, (uint32_t)((p / 3) & 1));
        }
        if (i + 2 < NCHUNK) load_stage((i + 2) % 3, i + 2);
        asm volatile("cp.async.commit_group;" ::: "memory");
    }
    {
        const int p = NCHUNK - 1;
        mbar_wait(sb + 8 + (p % 3) * 8, (uint32_t)((p / 3) & 1));
    }
    TC_FENCE_AFTER();

    // epilogue: D/M - mu_hs mu_hs^T - mu_hb mu_hb^T + eps I  (warps 0-3 only)
    if (wid < 4) {
        const float invM = 1.0f / (float)MDIM;
        const float* muHs = g_mu_hs + b * CDIM;
        const float* muHb = g_mu_hb + b * CDIM;
        const int r = ti * TILE + wid * 32 + lid;
        const float mhs_r = muHs[r];
        const float mhb_r = muHb[r];
        float* ob = out + (size_t)b * CDIM * CDIM;

#pragma unroll
        for (int cb = 0; cb < 4; cb++) {
            uint32_t regs[32];
            LDTM_X32(regs, tmem + cb * 32);
            TC_WAIT_LD();
            const int c0 = tj * TILE + cb * 32;
            float v[32];
#pragma unroll
            for (int j = 0; j < 32; j++) {
                const int c = c0 + j;
                float x = __uint_as_float(regs[j]) * invM - mhs_r * muHs[c] - mhb_r * muHb[c];
                if (c == r) x += 1e-8f;
                v[j] = x;
            }
            float4* dst = (float4*)(ob + (size_t)r * CDIM + c0);
#pragma unroll
            for (int q = 0; q < 8; q++)
                dst[q] = make_float4(v[q * 4], v[q * 4 + 1], v[q * 4 + 2], v[q * 4 + 3]);
            if (!diag) {
#pragma unroll
                for (int j = 0; j < 32; j++)
                    ob[(size_t)(c0 + j) * CDIM + r] = v[j];
            }
        }
        TC_FENCE_BEFORE();
    }
    __syncthreads();
    if (tid == 0) { MBAR_INVAL(sb + 8); MBAR_INVAL(sb + 16); MBAR_INVAL(sb + 24); }
    __syncthreads();
    if (wid == 0) TC_DEALLOC(tmem, 128);

#else
    // ======================= fp32 SIMT fallback (non-a pass) ================
    float* sA = (float*)smem;                   // [8][128]
    float* sB = sA + 8 * 128;                   // [8][128]
    const int tx = tid & 15;
    const int ty = tid >> 4;
    const int lc = tid >> 1;
    const int lq = (tid & 1) * 4;

    const __nv_bfloat16* Ahi = g_hi + (size_t)(b * CDIM + ti * TILE) * KTOT;
    const __nv_bfloat16* Alo = g_lo + (size_t)(b * CDIM + ti * TILE) * KTOT;
    const __nv_bfloat16* Bhi = g_hi + (size_t)(b * CDIM + tj * TILE) * KTOT;
    const __nv_bfloat16* Blo = g_lo + (size_t)(b * CDIM + tj * TILE) * KTOT;

    float acc[8][8];
#pragma unroll
    for (int r = 0; r < 8; r++)
#pragma unroll
        for (int s = 0; s < 8; s++) acc[r][s] = 0.f;

    for (int m0 = 0; m0 < KTOT; m0 += 8) {
        const size_t off = (size_t)lc * KTOT + m0 + lq;
        uint2 ah = *(const uint2*)(Ahi + off);
        uint2 al = *(const uint2*)(Alo + off);
        uint2 bh = *(const uint2*)(Bhi + off);
        uint2 bl = *(const uint2*)(Blo + off);
        float av[4], bv[4];
        const __nv_bfloat162* p;
        p = (const __nv_bfloat162*)&ah;
        av[0] = __bfloat162float(p[0].x); av[1] = __bfloat162float(p[0].y);
        av[2] = __bfloat162float(p[1].x); av[3] = __bfloat162float(p[1].y);
        p = (const __nv_bfloat162*)&al;
        av[0] += __bfloat162float(p[0].x); av[1] += __bfloat162float(p[0].y);
        av[2] += __bfloat162float(p[1].x); av[3] += __bfloat162float(p[1].y);
        p = (const __nv_bfloat162*)&bh;
        bv[0] = __bfloat162float(p[0].x); bv[1] = __bfloat162float(p[0].y);
        bv[2] = __bfloat162float(p[1].x); bv[3] = __bfloat162float(p[1].y);
        p = (const __nv_bfloat162*)&bl;
        bv[0] += __bfloat162float(p[0].x); bv[1] += __bfloat162float(p[0].y);
        bv[2] += __bfloat162float(p[1].x); bv[3] += __bfloat162float(p[1].y);

        __syncthreads();
#pragma unroll
        for (int j = 0; j < 4; j++) {
            sA[(lq + j) * 128 + lc] = av[j];
            sB[(lq + j) * 128 + lc] = bv[j];
        }
        __syncthreads();

#pragma unroll
        for (int k = 0; k < 8; k++) {
            float a8[8], b8[8];
            float4 x;
            x = *(const float4*)&sA[k * 128 + ty * 8];     a8[0]=x.x; a8[1]=x.y; a8[2]=x.z; a8[3]=x.w;
            x = *(const float4*)&sA[k * 128 + ty * 8 + 4]; a8[4]=x.x; a8[5]=x.y; a8[6]=x.z; a8[7]=x.w;
            x = *(const float4*)&sB[k * 128 + tx * 8];     b8[0]=x.x; b8[1]=x.y; b8[2]=x.z; b8[3]=x.w;
            x = *(const float4*)&sB[k * 128 + tx * 8 + 4]; b8[4]=x.x; b8[5]=x.y; b8[6]=x.z; b8[7]=x.w;
#pragma unroll
            for (int r = 0; r < 8; r++)
#pragma unroll
                for (int s = 0; s < 8; s++)
                    acc[r][s] += a8[r] * b8[s];
        }
    }

    const float invM = 1.0f / (float)MDIM;
    const float* muHs = g_mu_hs + b * CDIM;
    const float* muHb = g_mu_hb + b * CDIM;
    const int cbase = ti * TILE + ty * 8;
    const int dbase = tj * TILE + tx * 8;
    float* ob = out + (size_t)b * CDIM * CDIM;
#pragma unroll
    for (int r = 0; r < 8; r++) {
        const int cc = cbase + r;
#pragma unroll
        for (int s = 0; s < 8; s++) {
            const int dd = dbase + s;
            float v = acc[r][s] * invM - muHs[cc] * muHs[dd] - muHb[cc] * muHb[dd];
            if (cc == dd) v += 1e-8f;
            ob[(size_t)cc * CDIM + dd] = v;
            ob[(size_t)dd * CDIM + cc] = v;
        }
    }
#endif
}

// ---------------- launch ----------------------------------------------------
extern "C" void kernel_launch(void* const* d_in, const int* in_sizes, int n_in,
                              void* d_out, int out_size) {
    const float* h_in   = (const float*)d_in[0];
    const float* conv_w = (const float*)d_in[1];
    const float* conv_b = (const float*)d_in[2];
    float* out = (float*)d_out;

    static int configured = 0;
    if (!configured) {
        cudaFuncSetAttribute(syrk_tc, cudaFuncAttributeMaxDynamicSharedMemorySize, SMEM_DYN);
        configured = 1;
    }

    pe_kernel<<<CDIM, 256>>>();
    mean_kernel<<<BATCH * CDIM, 256>>>(h_in);
    gate_kernel<<<BATCH, CDIM>>>(conv_w, conv_b);
    split_kernel<<<BATCH * CDIM, 256>>>(h_in);
    syrk_tc<<<dim3(10, BATCH), 256, SMEM_DYN>>>(out);
}